// round 12
// baseline (speedup 1.0000x reference)
#include <cuda_runtime.h>
#include <cuda_bf16.h>
#include <cuda_fp16.h>
#include <cstdint>
#include <math.h>

typedef __nv_bfloat16 bf16;

#define BB   4
#define HW   4096
#define CC   512
#define GG   32
#define CPG  16
#define NPIX 16384
#define EPS  1e-5f

// scratch
__device__ uint8_t g_xn [(long)NPIX*CC];
__device__ uint8_t g_q  [(long)NPIX*CC];
__device__ uint8_t g_k  [(long)NPIX*CC];
__device__ uint8_t g_vt [(long)CC*NPIX];
__device__ uint8_t g_att[(long)NPIX*CC];
__device__ uint8_t g_p8 [(long)BB*HW*HW];   // fp8 scores -> fp8 probs*512 (in-place)
__device__ uint8_t g_wqt[CC*CC], g_wkt[CC*CC], g_wvt[CC*CC], g_wpt[CC*CC];
__device__ float   g_mean[BB*GG], g_rstd[BB*GG];

__device__ __forceinline__ uint32_t smem_u32(const void* p) {
    uint32_t a;
    asm("{ .reg .u64 t; cvta.to.shared.u64 t, %1; cvt.u32.u64 %0, t; }" : "=r"(a) : "l"(p));
    return a;
}
__device__ __forceinline__ uint16_t f2e4m3x2(float hi, float lo) {
    uint16_t u;
    asm("cvt.rn.satfinite.e4m3x2.f32 %0, %1, %2;" : "=h"(u) : "f"(hi), "f"(lo));
    return u;
}
__device__ __forceinline__ __half2 e4m3x2_2h(uint16_t u) {
    uint32_t r;
    asm("cvt.rn.f16x2.e4m3x2 %0, %1;" : "=r"(r) : "h"(u));
    return *(__half2*)&r;
}
#define CP16(s, g) asm volatile("cp.async.cg.shared.global [%0], [%1], 16;" :: "r"(s), "l"(g) : "memory")
#define CP_COMMIT() asm volatile("cp.async.commit_group;" ::: "memory")
#define CP_WAIT(n)  asm volatile("cp.async.wait_group %0;" :: "n"(n) : "memory")
#define LDSM4(r0,r1,r2,r3,a) asm volatile( \
    "ldmatrix.sync.aligned.m8n8.x4.shared.b16 {%0,%1,%2,%3}, [%4];" \
    : "=r"(r0),"=r"(r1),"=r"(r2),"=r"(r3) : "r"(a))
#define MMAFP8(c0,c1,c2,c3,a0,a1,a2,a3,b0,b1) asm volatile( \
    "mma.sync.aligned.m16n8k32.row.col.f32.e4m3.e4m3.f32 " \
    "{%0,%1,%2,%3}, {%4,%5,%6,%7}, {%8,%9}, {%0,%1,%2,%3};" \
    : "+f"(c0),"+f"(c1),"+f"(c2),"+f"(c3) \
    : "r"(a0),"r"(a1),"r"(a2),"r"(a3),"r"(b0),"r"(b1))

// ---------------- GroupNorm ---------------------------------------------------
__global__ void gn_stats(const float* __restrict__ x, float* __restrict__ mo, float* __restrict__ ro)
{
    int bg = blockIdx.x, b = bg >> 5, g = bg & 31;
    const float* base = x + (long)b*HW*CC + g*CPG;
    int tid = threadIdx.x;
    float s = 0.f, ss = 0.f;
    for (int p = tid; p < HW; p += 256) {
        const float4* q4 = (const float4*)(base + (long)p*CC);
        #pragma unroll
        for (int i = 0; i < 4; i++) {
            float4 t = q4[i];
            s  += t.x + t.y + t.z + t.w;
            ss += t.x*t.x + t.y*t.y + t.z*t.z + t.w*t.w;
        }
    }
    __shared__ float rs[256], rss[256];
    rs[tid] = s; rss[tid] = ss;
    __syncthreads();
    for (int st = 128; st > 0; st >>= 1) {
        if (tid < st) { rs[tid] += rs[tid+st]; rss[tid] += rss[tid+st]; }
        __syncthreads();
    }
    if (tid == 0) {
        const float inv = 1.f / (float)(HW*CPG);
        float m = rs[0]*inv, var = rss[0]*inv - m*m;
        mo[bg] = m; ro[bg] = rsqrtf(var + EPS);
    }
}

__global__ void gn_apply(const float* __restrict__ x, const float* __restrict__ gamma,
                         const float* __restrict__ beta, const float* __restrict__ mean,
                         const float* __restrict__ rstd, uint8_t* __restrict__ xn)
{
    long idx = (long)blockIdx.x*256 + threadIdx.x;
    int  c4  = (int)(idx & 127) * 4;
    int  b   = (int)(idx >> 19);
    int  g   = c4 >> 4;
    float m = mean[b*GG + g], r = rstd[b*GG + g];
    float4 xv = ((const float4*)x)[idx];
    float4 gv = ((const float4*)gamma)[c4 >> 2];
    float4 bv = ((const float4*)beta )[c4 >> 2];
    float v0 = (xv.x-m)*r*gv.x + bv.x, v1 = (xv.y-m)*r*gv.y + bv.y;
    float v2 = (xv.z-m)*r*gv.z + bv.z, v3 = (xv.w-m)*r*gv.w + bv.w;
    uint32_t o = (uint32_t)f2e4m3x2(v1, v0) | ((uint32_t)f2e4m3x2(v3, v2) << 16);
    ((uint32_t*)xn)[idx] = o;
}

// all 4 weight transposes fp32 -> fp8 x64 in one launch
__global__ void wtrans_all(const float* __restrict__ W0, const float* __restrict__ W1,
                           const float* __restrict__ W2, const float* __restrict__ W3,
                           uint8_t* __restrict__ T0, uint8_t* __restrict__ T1,
                           uint8_t* __restrict__ T2, uint8_t* __restrict__ T3)
{
    const float* W = (blockIdx.z == 0) ? W0 : (blockIdx.z == 1) ? W1 : (blockIdx.z == 2) ? W2 : W3;
    uint8_t*    WT = (blockIdx.z == 0) ? T0 : (blockIdx.z == 1) ? T1 : (blockIdx.z == 2) ? T2 : T3;
    __shared__ float t[32][33];
    int bx = blockIdx.x*32, by = blockIdx.y*32;
    int x = threadIdx.x, y = threadIdx.y;
    #pragma unroll
    for (int i = 0; i < 32; i += 8) t[y+i][x] = W[(long)(by+y+i)*CC + bx + x];
    __syncthreads();
    #pragma unroll
    for (int i = 0; i < 32; i += 8) {
        uint16_t u = f2e4m3x2(0.f, t[x][y+i] * 64.f);
        WT[(long)(bx+y+i)*CC + by + x] = (uint8_t)(u & 0xFF);
    }
}

// ---------------- fp8 mma.sync GEMM: C[M,N] = scale*A@B^T (+bias/res) ----------
// Tile 128x128, K-chunk 128 (4 kp-steps), 3 smem stages.
#define TM 128
#define TN 128
#define TK 128
#define STAGES 3
#define ROWB 144                   // 128B data + 16B pad (conflict-free ldmatrix)
#define A_SZ (128*ROWB)            // 18432
#define STGB (2*A_SZ)              // 36864
#define GEMM_DSMEM (STAGES*STGB)   // 110592

__global__ void __launch_bounds__(256, 2)
gemm_f8(const uint8_t* __restrict__ A, const uint8_t* __restrict__ B,
        long ldA, long ldB, int kChunks,
        int aRowMul, int bRowMul, long bKMul,
        void* __restrict__ Cout, long ldC, long cZStride, int outType, // 1=f32 2=fp8
        const float* __restrict__ colBias, const float* __restrict__ rowBias,
        const float* __restrict__ res, float scale)
{
    extern __shared__ char dyn[];
    uint32_t smem0 = smem_u32(dyn);
    int tid = threadIdx.x, wid = tid >> 5, lane = tid & 31;
    int warp_m = wid >> 2, warp_n = wid & 3;
    int z = blockIdx.z;
    long bm = (long)blockIdx.y * TM;
    long bn = (long)blockIdx.x * TN;

    const uint8_t* baseA = A + ((long)z*aRowMul + bm) * ldA;
    const uint8_t* baseB = B + ((long)z*bRowMul + bn) * ldB + (long)z*bKMul;

    // per-thread load mapping: 128 rows x 8 cols of 16B; 4 iterations each for A,B
    int lrow = tid >> 3, lcol = tid & 7;            // rows 0..31 (+32 per iter)
    const uint8_t* gA = baseA + (long)lrow*ldA + lcol*16;
    const uint8_t* gB = baseB + (long)lrow*ldB + lcol*16;
    uint32_t sOf = (uint32_t)(lrow*ROWB + lcol*16); // +32*ROWB per iter

    uint32_t aoff[4], boff[2];
    #pragma unroll
    for (int mt = 0; mt < 4; mt++)
        aoff[mt] = (uint32_t)((warp_m*64 + mt*16 + (lane & 15))*ROWB + (lane >> 4)*16);
    #pragma unroll
    for (int np = 0; np < 2; np++)
        boff[np] = (uint32_t)((warp_n*32 + np*16 + ((lane >> 4) & 1)*8 + (lane & 7))*ROWB
                              + ((lane >> 3) & 1)*16);

    float acc[4][4][4];
    #pragma unroll
    for (int i = 0; i < 4; i++)
        #pragma unroll
        for (int j = 0; j < 4; j++)
            #pragma unroll
            for (int r = 0; r < 4; r++) acc[i][j][r] = 0.f;

    // prologue: issue STAGES-1 = 2 chunk loads
    #pragma unroll
    for (int s = 0; s < STAGES-1; s++) {
        uint32_t sA = smem0 + s*STGB, sB = sA + A_SZ;
        #pragma unroll
        for (int i = 0; i < 4; i++) {
            CP16(sA + sOf + i*(32*ROWB), gA + (long)i*32*ldA + s*TK);
            CP16(sB + sOf + i*(32*ROWB), gB + (long)i*32*ldB + s*TK);
        }
        CP_COMMIT();
    }
    const uint8_t* pA = gA + (STAGES-1)*TK;
    const uint8_t* pB = gB + (STAGES-1)*TK;
    int stage = 0, nstage = STAGES-1;

    for (int c = 0; c < kChunks; c++) {
        CP_WAIT(STAGES-2);
        __syncthreads();

        uint32_t sA = smem0 + stage*STGB;
        uint32_t sB = sA + A_SZ;
        if (++stage == STAGES) stage = 0;

        // kp0
        uint32_t a[16], b[8];
        #pragma unroll
        for (int mt = 0; mt < 4; mt++)
            LDSM4(a[mt*4], a[mt*4+1], a[mt*4+2], a[mt*4+3], sA + aoff[mt]);
        #pragma unroll
        for (int np = 0; np < 2; np++)
            LDSM4(b[np*4], b[np*4+1], b[np*4+2], b[np*4+3], sB + boff[np]);
        #pragma unroll
        for (int mt = 0; mt < 4; mt++)
            #pragma unroll
            for (int nt = 0; nt < 4; nt++) {
                int bi = (nt >> 1)*4 + (nt & 1)*2;
                MMAFP8(acc[mt][nt][0], acc[mt][nt][1], acc[mt][nt][2], acc[mt][nt][3],
                       a[mt*4], a[mt*4+1], a[mt*4+2], a[mt*4+3], b[bi], b[bi+1]);
            }

        // issue next-chunk loads (covered by tensor work)
        if (c + STAGES - 1 < kChunks) {
            uint32_t nA = smem0 + nstage*STGB, nB = nA + A_SZ;
            #pragma unroll
            for (int i = 0; i < 4; i++) {
                CP16(nA + sOf + i*(32*ROWB), pA + (long)i*32*ldA);
                CP16(nB + sOf + i*(32*ROWB), pB + (long)i*32*ldB);
            }
            pA += TK; pB += TK;
        }
        CP_COMMIT();
        if (++nstage == STAGES) nstage = 0;

        // kp1..kp3
        #pragma unroll
        for (int kp = 1; kp < 4; kp++) {
            #pragma unroll
            for (int mt = 0; mt < 4; mt++)
                LDSM4(a[mt*4], a[mt*4+1], a[mt*4+2], a[mt*4+3], sA + aoff[mt] + kp*32);
            #pragma unroll
            for (int np = 0; np < 2; np++)
                LDSM4(b[np*4], b[np*4+1], b[np*4+2], b[np*4+3], sB + boff[np] + kp*32);
            #pragma unroll
            for (int mt = 0; mt < 4; mt++)
                #pragma unroll
                for (int nt = 0; nt < 4; nt++) {
                    int bi = (nt >> 1)*4 + (nt & 1)*2;
                    MMAFP8(acc[mt][nt][0], acc[mt][nt][1], acc[mt][nt][2], acc[mt][nt][3],
                           a[mt*4], a[mt*4+1], a[mt*4+2], a[mt*4+3], b[bi], b[bi+1]);
                }
        }
    }
    CP_WAIT(0);
    __syncthreads();

    int rbase = warp_m*64 + (lane >> 2);
    int cbase = warp_n*32 + (lane & 3)*2;

    if (outType == 2) {          // fp8
        const int RS = TN + 16;
        #pragma unroll
        for (int mt = 0; mt < 4; mt++)
            #pragma unroll
            for (int nt = 0; nt < 4; nt++) {
                int col = cbase + nt*8;
                float cb0 = colBias ? colBias[bn + col]     : 0.f;
                float cb1 = colBias ? colBias[bn + col + 1] : 0.f;
                #pragma unroll
                for (int h = 0; h < 2; h++) {
                    int row = rbase + mt*16 + h*8;
                    float rb = rowBias ? rowBias[bm + row] : 0.f;
                    float v0 = acc[mt][nt][2*h]  *scale + rb + cb0;
                    float v1 = acc[mt][nt][2*h+1]*scale + rb + cb1;
                    *(uint16_t*)(dyn + row*RS + col) = f2e4m3x2(v1, v0);
                }
            }
        __syncthreads();
        uint8_t* C = (uint8_t*)Cout + (long)z*cZStride + bm*ldC + bn;
        #pragma unroll
        for (int it = 0; it < 4; it++) {
            int m = tid + it*256;
            int r = m >> 3, i = m & 7;
            *(uint4*)(C + (long)r*ldC + i*16) = *(uint4*)(dyn + r*RS + i*16);
        }
    } else {                     // f32 (+res)
        const int RS = TN*4 + 16;
        #pragma unroll
        for (int mt = 0; mt < 4; mt++)
            #pragma unroll
            for (int nt = 0; nt < 4; nt++) {
                int col = cbase + nt*8;
                float cb0 = colBias ? colBias[bn + col]     : 0.f;
                float cb1 = colBias ? colBias[bn + col + 1] : 0.f;
                #pragma unroll
                for (int h = 0; h < 2; h++) {
                    int row = rbase + mt*16 + h*8;
                    float rb = rowBias ? rowBias[bm + row] : 0.f;
                    float2 v;
                    v.x = acc[mt][nt][2*h]  *scale + rb + cb0;
                    v.y = acc[mt][nt][2*h+1]*scale + rb + cb1;
                    *(float2*)(dyn + row*RS + col*4) = v;
                }
            }
        __syncthreads();
        float* C = (float*)Cout + (long)z*cZStride + bm*ldC + bn;
        const float* R = res ? res + (long)z*cZStride + bm*ldC + bn : nullptr;
        #pragma unroll
        for (int it = 0; it < 16; it++) {
            int m = tid + it*256;
            int r = m >> 5, i = m & 31;
            float4 v = *(float4*)(dyn + r*RS + i*16);
            if (R) {
                float4 rr = *(const float4*)(R + (long)r*ldC + i*4);
                v.x += rr.x; v.y += rr.y; v.z += rr.z; v.w += rr.w;
            }
            *(float4*)(C + (long)r*ldC + i*4) = v;
        }
    }
}

// ---------------- softmax: fp8 scores -> fp8 probs*512, in place ---------------
__global__ void softmax_f8(uint8_t* __restrict__ S)
{
    uint8_t* p = S + (long)blockIdx.x * HW;
    int tid = threadIdx.x;               // 256 threads * 16 fp8
    uint4 u = ((uint4*)p)[tid];
    uint16_t* hp = (uint16_t*)&u;
    float v[16];
    #pragma unroll
    for (int i = 0; i < 8; i++) {
        __half2 h = e4m3x2_2h(hp[i]);
        v[2*i] = __low2float(h); v[2*i+1] = __high2float(h);
    }
    float mx = -1e30f;
    #pragma unroll
    for (int i = 0; i < 16; i++) mx = fmaxf(mx, v[i]);
    __shared__ float red[256];
    red[tid] = mx; __syncthreads();
    for (int s = 128; s > 0; s >>= 1) {
        if (tid < s) red[tid] = fmaxf(red[tid], red[tid+s]);
        __syncthreads();
    }
    mx = red[0]; __syncthreads();
    float sum = 0.f;
    #pragma unroll
    for (int i = 0; i < 16; i++) { v[i] = __expf(v[i] - mx); sum += v[i]; }
    red[tid] = sum; __syncthreads();
    for (int s = 128; s > 0; s >>= 1) {
        if (tid < s) red[tid] += red[tid+s];
        __syncthreads();
    }
    float inv = 512.f / red[0];
    #pragma unroll
    for (int i = 0; i < 8; i++) hp[i] = f2e4m3x2(v[2*i+1]*inv, v[2*i]*inv);
    ((uint4*)p)[tid] = u;
}

// ---------------- host -----------------------------------------------------------
extern "C" void kernel_launch(void* const* d_in, const int* in_sizes, int n_in,
                              void* d_out, int out_size)
{
    const float* x     = (const float*)d_in[0];
    const float* gamma = (const float*)d_in[1];
    const float* beta  = (const float*)d_in[2];
    const float* Wq    = (const float*)d_in[3];
    const float* bq    = (const float*)d_in[4];
    const float* Wk    = (const float*)d_in[5];
    const float* bk    = (const float*)d_in[6];
    const float* Wv    = (const float*)d_in[7];
    const float* bv    = (const float*)d_in[8];
    const float* Wp    = (const float*)d_in[9];
    const float* bp    = (const float*)d_in[10];
    float* out = (float*)d_out;

    static uint8_t *xn=nullptr, *q=nullptr, *k=nullptr, *vt=nullptr, *att=nullptr, *p8=nullptr;
    static uint8_t *wqt=nullptr, *wkt=nullptr, *wvt=nullptr, *wpt=nullptr;
    static float *mean=nullptr, *rstd=nullptr;
    if (!xn) {
        cudaGetSymbolAddress((void**)&xn,  g_xn);  cudaGetSymbolAddress((void**)&q,   g_q);
        cudaGetSymbolAddress((void**)&k,   g_k);   cudaGetSymbolAddress((void**)&vt,  g_vt);
        cudaGetSymbolAddress((void**)&att, g_att); cudaGetSymbolAddress((void**)&p8,  g_p8);
        cudaGetSymbolAddress((void**)&wqt, g_wqt); cudaGetSymbolAddress((void**)&wkt, g_wkt);
        cudaGetSymbolAddress((void**)&wvt, g_wvt); cudaGetSymbolAddress((void**)&wpt, g_wpt);
        cudaGetSymbolAddress((void**)&mean, g_mean); cudaGetSymbolAddress((void**)&rstd, g_rstd);
        cudaFuncSetAttribute(gemm_f8, cudaFuncAttributeMaxDynamicSharedMemorySize, GEMM_DSMEM);
    }

    const float iw = 1.f/64.f;                   // undo weight x64
    const float sscale = 0.044194173824159216f;  // 1/sqrt(512)

    // launch order: ncu captures launch idx 5 -> scores GEMM
    gn_stats<<<BB*GG, 256>>>(x, mean, rstd);                                    // 0
    gn_apply<<<NPIX*CC/4/256, 256>>>(x, gamma, beta, mean, rstd, xn);           // 1
    wtrans_all<<<dim3(16,16,4), dim3(32,8)>>>(Wq, Wk, Wv, Wp,
                                              wqt, wkt, wvt, wpt);              // 2
    gemm_f8<<<dim3(CC/TN, NPIX/TM, 1), 256, GEMM_DSMEM>>>(
        xn, wqt, CC, CC, CC/TK, 0, 0, 0, q, CC, 0, 2, bq, nullptr, nullptr, iw);   // 3
    gemm_f8<<<dim3(CC/TN, NPIX/TM, 1), 256, GEMM_DSMEM>>>(
        xn, wkt, CC, CC, CC/TK, 0, 0, 0, k, CC, 0, 2, bk, nullptr, nullptr, iw);   // 4
    // scores = q @ k^T / sqrt(512) -> fp8 (ncu target)
    gemm_f8<<<dim3(HW/TN, HW/TM, BB), 256, GEMM_DSMEM>>>(
        q, k, CC, CC, CC/TK, HW, HW, 0, p8, HW, (long)HW*HW, 2,
        nullptr, nullptr, nullptr, sscale);                                        // 5
    gemm_f8<<<dim3(NPIX/TN, CC/TM, 1), 256, GEMM_DSMEM>>>(
        wvt, xn, CC, CC, CC/TK, 0, 0, 0, vt, NPIX, 0, 2, nullptr, bv, nullptr, iw);// 6
    softmax_f8<<<BB*HW, 256>>>(p8);                                                // 7
    // att8 = (P*512 @ V)*(64/512) = att*64 -> fp8
    gemm_f8<<<dim3(CC/TN, HW/TM, BB), 256, GEMM_DSMEM>>>(
        p8, vt, HW, NPIX, HW/TK, HW, 0, HW, att, CC, (long)HW*CC, 2,
        nullptr, nullptr, nullptr, 0.125f);                                        // 8
    // out = (att*64 @ Wp*64)/4096 + bp + x  (fp32)
    gemm_f8<<<dim3(CC/TN, NPIX/TM, 1), 256, GEMM_DSMEM>>>(
        att, wpt, CC, CC, CC/TK, 0, 0, 0, out, CC, 0, 1,
        bp, nullptr, x, 1.f/4096.f);                                               // 9
}

// round 14
// speedup vs baseline: 1.0397x; 1.0397x over previous
#include <cuda_runtime.h>
#include <cuda_bf16.h>
#include <cuda_fp16.h>
#include <cstdint>
#include <math.h>

typedef __nv_bfloat16 bf16;

#define BB   4
#define HW   4096
#define CC   512
#define GG   32
#define CPG  16
#define NPIX 16384
#define EPS  1e-5f

// scratch
__device__ uint8_t g_xn [(long)NPIX*CC];
__device__ uint8_t g_q  [(long)NPIX*CC];
__device__ uint8_t g_k  [(long)NPIX*CC];
__device__ uint8_t g_vt [(long)CC*NPIX];
__device__ uint8_t g_att[(long)NPIX*CC];
__device__ uint8_t g_p8 [(long)BB*HW*HW];   // fp8 scores -> fp8 probs*512 (in-place)
__device__ uint8_t g_wqt[CC*CC], g_wkt[CC*CC], g_wvt[CC*CC], g_wpt[CC*CC];
__device__ float   g_mean[BB*GG], g_rstd[BB*GG];

__device__ __forceinline__ uint32_t smem_u32(const void* p) {
    uint32_t a;
    asm("{ .reg .u64 t; cvta.to.shared.u64 t, %1; cvt.u32.u64 %0, t; }" : "=r"(a) : "l"(p));
    return a;
}
__device__ __forceinline__ uint16_t f2e4m3x2(float hi, float lo) {
    uint16_t u;
    asm("cvt.rn.satfinite.e4m3x2.f32 %0, %1, %2;" : "=h"(u) : "f"(hi), "f"(lo));
    return u;
}
__device__ __forceinline__ __half2 e4m3x2_2h(uint16_t u) {
    uint32_t r;
    asm("cvt.rn.f16x2.e4m3x2 %0, %1;" : "=r"(r) : "h"(u));
    return *(__half2*)&r;
}
#define CP16(s, g) asm volatile("cp.async.cg.shared.global [%0], [%1], 16;" :: "r"(s), "l"(g) : "memory")
#define CP_COMMIT() asm volatile("cp.async.commit_group;" ::: "memory")
#define CP_WAIT(n)  asm volatile("cp.async.wait_group %0;" :: "n"(n) : "memory")
#define LDSM4(r0,r1,r2,r3,a) asm volatile( \
    "ldmatrix.sync.aligned.m8n8.x4.shared.b16 {%0,%1,%2,%3}, [%4];" \
    : "=r"(r0),"=r"(r1),"=r"(r2),"=r"(r3) : "r"(a))
#define MMAFP8(c0,c1,c2,c3,a0,a1,a2,a3,b0,b1) asm volatile( \
    "mma.sync.aligned.m16n8k32.row.col.f32.e4m3.e4m3.f32 " \
    "{%0,%1,%2,%3}, {%4,%5,%6,%7}, {%8,%9}, {%0,%1,%2,%3};" \
    : "+f"(c0),"+f"(c1),"+f"(c2),"+f"(c3) \
    : "r"(a0),"r"(a1),"r"(a2),"r"(a3),"r"(b0),"r"(b1))
#define MMAFP8H(c0,c1,a0,a1,a2,a3,b0,b1) asm volatile( \
    "mma.sync.aligned.m16n8k32.row.col.f16.e4m3.e4m3.f16 " \
    "{%0,%1}, {%2,%3,%4,%5}, {%6,%7}, {%0,%1};" \
    : "+r"(c0),"+r"(c1) \
    : "r"(a0),"r"(a1),"r"(a2),"r"(a3),"r"(b0),"r"(b1))

// ---------------- GroupNorm ---------------------------------------------------
__global__ void gn_stats(const float* __restrict__ x, float* __restrict__ mo, float* __restrict__ ro)
{
    int bg = blockIdx.x, b = bg >> 5, g = bg & 31;
    const float* base = x + (long)b*HW*CC + g*CPG;
    int tid = threadIdx.x;
    float s = 0.f, ss = 0.f;
    for (int p = tid; p < HW; p += 256) {
        const float4* q4 = (const float4*)(base + (long)p*CC);
        #pragma unroll
        for (int i = 0; i < 4; i++) {
            float4 t = q4[i];
            s  += t.x + t.y + t.z + t.w;
            ss += t.x*t.x + t.y*t.y + t.z*t.z + t.w*t.w;
        }
    }
    __shared__ float rs[256], rss[256];
    rs[tid] = s; rss[tid] = ss;
    __syncthreads();
    for (int st = 128; st > 0; st >>= 1) {
        if (tid < st) { rs[tid] += rs[tid+st]; rss[tid] += rss[tid+st]; }
        __syncthreads();
    }
    if (tid == 0) {
        const float inv = 1.f / (float)(HW*CPG);
        float m = rs[0]*inv, var = rss[0]*inv - m*m;
        mo[bg] = m; ro[bg] = rsqrtf(var + EPS);
    }
}

__global__ void gn_apply(const float* __restrict__ x, const float* __restrict__ gamma,
                         const float* __restrict__ beta, const float* __restrict__ mean,
                         const float* __restrict__ rstd, uint8_t* __restrict__ xn)
{
    long idx = (long)blockIdx.x*256 + threadIdx.x;
    int  c4  = (int)(idx & 127) * 4;
    int  b   = (int)(idx >> 19);
    int  g   = c4 >> 4;
    float m = mean[b*GG + g], r = rstd[b*GG + g];
    float4 xv = ((const float4*)x)[idx];
    float4 gv = ((const float4*)gamma)[c4 >> 2];
    float4 bv = ((const float4*)beta )[c4 >> 2];
    float v0 = (xv.x-m)*r*gv.x + bv.x, v1 = (xv.y-m)*r*gv.y + bv.y;
    float v2 = (xv.z-m)*r*gv.z + bv.z, v3 = (xv.w-m)*r*gv.w + bv.w;
    uint32_t o = (uint32_t)f2e4m3x2(v1, v0) | ((uint32_t)f2e4m3x2(v3, v2) << 16);
    ((uint32_t*)xn)[idx] = o;
}

// all 4 weight transposes fp32 -> fp8 x64 in one launch
__global__ void wtrans_all(const float* __restrict__ W0, const float* __restrict__ W1,
                           const float* __restrict__ W2, const float* __restrict__ W3,
                           uint8_t* __restrict__ T0, uint8_t* __restrict__ T1,
                           uint8_t* __restrict__ T2, uint8_t* __restrict__ T3)
{
    const float* W = (blockIdx.z == 0) ? W0 : (blockIdx.z == 1) ? W1 : (blockIdx.z == 2) ? W2 : W3;
    uint8_t*    WT = (blockIdx.z == 0) ? T0 : (blockIdx.z == 1) ? T1 : (blockIdx.z == 2) ? T2 : T3;
    __shared__ float t[32][33];
    int bx = blockIdx.x*32, by = blockIdx.y*32;
    int x = threadIdx.x, y = threadIdx.y;
    #pragma unroll
    for (int i = 0; i < 32; i += 8) t[y+i][x] = W[(long)(by+y+i)*CC + bx + x];
    __syncthreads();
    #pragma unroll
    for (int i = 0; i < 32; i += 8) {
        uint16_t u = f2e4m3x2(0.f, t[x][y+i] * 64.f);
        WT[(long)(bx+y+i)*CC + by + x] = (uint8_t)(u & 0xFF);
    }
}

// ---------------- fp8 mma.sync GEMM: C[M,N] = scale*A@B^T (+bias/res) ----------
// Tile 128x128, K-chunk 128 (4 kp-steps), 3 smem stages.
// ACCF16: f16 accumulators (attention GEMMs only).
#define TM 128
#define TN 128
#define TK 128
#define STAGES 3
#define ROWB 144
#define A_SZ (128*ROWB)
#define STGB (2*A_SZ)
#define GEMM_DSMEM (STAGES*STGB)   // 110592

template<bool ACCF16>
__global__ void __launch_bounds__(256, 2)
gemm_f8(const uint8_t* __restrict__ A, const uint8_t* __restrict__ B,
        long ldA, long ldB, int kChunks,
        int aRowMul, int bRowMul, long bKMul,
        void* __restrict__ Cout, long ldC, long cZStride, int outType, // 1=f32 2=fp8
        const float* __restrict__ colBias, const float* __restrict__ rowBias,
        const float* __restrict__ res, float scale)
{
    extern __shared__ char dyn[];
    uint32_t smem0 = smem_u32(dyn);
    int tid = threadIdx.x, wid = tid >> 5, lane = tid & 31;
    int warp_m = wid >> 2, warp_n = wid & 3;
    int z = blockIdx.z;
    long bm = (long)blockIdx.y * TM;
    long bn = (long)blockIdx.x * TN;

    const uint8_t* baseA = A + ((long)z*aRowMul + bm) * ldA;
    const uint8_t* baseB = B + ((long)z*bRowMul + bn) * ldB + (long)z*bKMul;

    int lrow = tid >> 3, lcol = tid & 7;
    const uint8_t* gA = baseA + (long)lrow*ldA + lcol*16;
    const uint8_t* gB = baseB + (long)lrow*ldB + lcol*16;
    uint32_t sOf = (uint32_t)(lrow*ROWB + lcol*16);

    uint32_t aoff[4], boff[2];
    #pragma unroll
    for (int mt = 0; mt < 4; mt++)
        aoff[mt] = (uint32_t)((warp_m*64 + mt*16 + (lane & 15))*ROWB + (lane >> 4)*16);
    #pragma unroll
    for (int np = 0; np < 2; np++)
        boff[np] = (uint32_t)((warp_n*32 + np*16 + ((lane >> 4) & 1)*8 + (lane & 7))*ROWB
                              + ((lane >> 3) & 1)*16);

    float    fa[ACCF16 ? 1 : 4][4][4];
    uint32_t ha[ACCF16 ? 4 : 1][4][2];
    if constexpr (ACCF16) {
        #pragma unroll
        for (int i = 0; i < 4; i++)
            #pragma unroll
            for (int j = 0; j < 4; j++) { ha[i][j][0] = 0u; ha[i][j][1] = 0u; }
    } else {
        #pragma unroll
        for (int i = 0; i < 4; i++)
            #pragma unroll
            for (int j = 0; j < 4; j++)
                #pragma unroll
                for (int r = 0; r < 4; r++) fa[i][j][r] = 0.f;
    }

    #pragma unroll
    for (int s = 0; s < STAGES-1; s++) {
        uint32_t sA = smem0 + s*STGB, sB = sA + A_SZ;
        #pragma unroll
        for (int i = 0; i < 4; i++) {
            CP16(sA + sOf + i*(32*ROWB), gA + (long)i*32*ldA + s*TK);
            CP16(sB + sOf + i*(32*ROWB), gB + (long)i*32*ldB + s*TK);
        }
        CP_COMMIT();
    }
    const uint8_t* pA = gA + (STAGES-1)*TK;
    const uint8_t* pB = gB + (STAGES-1)*TK;
    int stage = 0, nstage = STAGES-1;

    for (int c = 0; c < kChunks; c++) {
        CP_WAIT(STAGES-2);
        __syncthreads();

        uint32_t sA = smem0 + stage*STGB;
        uint32_t sB = sA + A_SZ;
        if (++stage == STAGES) stage = 0;

        // kp0
        uint32_t a[16], b[8];
        #pragma unroll
        for (int mt = 0; mt < 4; mt++)
            LDSM4(a[mt*4], a[mt*4+1], a[mt*4+2], a[mt*4+3], sA + aoff[mt]);
        #pragma unroll
        for (int np = 0; np < 2; np++)
            LDSM4(b[np*4], b[np*4+1], b[np*4+2], b[np*4+3], sB + boff[np]);
        #pragma unroll
        for (int mt = 0; mt < 4; mt++)
            #pragma unroll
            for (int nt = 0; nt < 4; nt++) {
                int bi = (nt >> 1)*4 + (nt & 1)*2;
                if constexpr (ACCF16)
                    MMAFP8H(ha[mt][nt][0], ha[mt][nt][1],
                            a[mt*4], a[mt*4+1], a[mt*4+2], a[mt*4+3], b[bi], b[bi+1]);
                else
                    MMAFP8(fa[mt][nt][0], fa[mt][nt][1], fa[mt][nt][2], fa[mt][nt][3],
                           a[mt*4], a[mt*4+1], a[mt*4+2], a[mt*4+3], b[bi], b[bi+1]);
            }

        if (c + STAGES - 1 < kChunks) {
            uint32_t nA = smem0 + nstage*STGB, nB = nA + A_SZ;
            #pragma unroll
            for (int i = 0; i < 4; i++) {
                CP16(nA + sOf + i*(32*ROWB), pA + (long)i*32*ldA);
                CP16(nB + sOf + i*(32*ROWB), pB + (long)i*32*ldB);
            }
            pA += TK; pB += TK;
        }
        CP_COMMIT();
        if (++nstage == STAGES) nstage = 0;

        // kp1..kp3
        #pragma unroll
        for (int kp = 1; kp < 4; kp++) {
            #pragma unroll
            for (int mt = 0; mt < 4; mt++)
                LDSM4(a[mt*4], a[mt*4+1], a[mt*4+2], a[mt*4+3], sA + aoff[mt] + kp*32);
            #pragma unroll
            for (int np = 0; np < 2; np++)
                LDSM4(b[np*4], b[np*4+1], b[np*4+2], b[np*4+3], sB + boff[np] + kp*32);
            #pragma unroll
            for (int mt = 0; mt < 4; mt++)
                #pragma unroll
                for (int nt = 0; nt < 4; nt++) {
                    int bi = (nt >> 1)*4 + (nt & 1)*2;
                    if constexpr (ACCF16)
                        MMAFP8H(ha[mt][nt][0], ha[mt][nt][1],
                                a[mt*4], a[mt*4+1], a[mt*4+2], a[mt*4+3], b[bi], b[bi+1]);
                    else
                        MMAFP8(fa[mt][nt][0], fa[mt][nt][1], fa[mt][nt][2], fa[mt][nt][3],
                               a[mt*4], a[mt*4+1], a[mt*4+2], a[mt*4+3], b[bi], b[bi+1]);
                }
        }
    }
    CP_WAIT(0);
    __syncthreads();

    int rbase = warp_m*64 + (lane >> 2);
    int cbase = warp_n*32 + (lane & 3)*2;

    if (outType == 2) {          // fp8
        const int RS = TN + 16;
        #pragma unroll
        for (int mt = 0; mt < 4; mt++)
            #pragma unroll
            for (int nt = 0; nt < 4; nt++) {
                int col = cbase + nt*8;
                float cb0 = colBias ? colBias[bn + col]     : 0.f;
                float cb1 = colBias ? colBias[bn + col + 1] : 0.f;
                #pragma unroll
                for (int h = 0; h < 2; h++) {
                    int row = rbase + mt*16 + h*8;
                    float rb = rowBias ? rowBias[bm + row] : 0.f;
                    float u0, u1;
                    if constexpr (ACCF16) {
                        __half2 hh = *(__half2*)&ha[mt][nt][h];
                        u0 = __low2float(hh); u1 = __high2float(hh);
                    } else { u0 = fa[mt][nt][2*h]; u1 = fa[mt][nt][2*h+1]; }
                    float v0 = u0*scale + rb + cb0;
                    float v1 = u1*scale + rb + cb1;
                    *(uint16_t*)(dyn + row*RS + col) = f2e4m3x2(v1, v0);
                }
            }
        __syncthreads();
        uint8_t* C = (uint8_t*)Cout + (long)z*cZStride + bm*ldC + bn;
        #pragma unroll
        for (int it = 0; it < 4; it++) {
            int m = tid + it*256;
            int r = m >> 3, i = m & 7;
            *(uint4*)(C + (long)r*ldC + i*16) = *(uint4*)(dyn + r*RS + i*16);
        }
    } else {                     // f32 (+res)
        const int RS = TN*4 + 16;
        #pragma unroll
        for (int mt = 0; mt < 4; mt++)
            #pragma unroll
            for (int nt = 0; nt < 4; nt++) {
                int col = cbase + nt*8;
                float cb0 = colBias ? colBias[bn + col]     : 0.f;
                float cb1 = colBias ? colBias[bn + col + 1] : 0.f;
                #pragma unroll
                for (int h = 0; h < 2; h++) {
                    int row = rbase + mt*16 + h*8;
                    float rb = rowBias ? rowBias[bm + row] : 0.f;
                    float u0, u1;
                    if constexpr (ACCF16) {
                        __half2 hh = *(__half2*)&ha[mt][nt][h];
                        u0 = __low2float(hh); u1 = __high2float(hh);
                    } else { u0 = fa[mt][nt][2*h]; u1 = fa[mt][nt][2*h+1]; }
                    float2 v;
                    v.x = u0*scale + rb + cb0;
                    v.y = u1*scale + rb + cb1;
                    *(float2*)(dyn + row*RS + col*4) = v;
                }
            }
        __syncthreads();
        float* C = (float*)Cout + (long)z*cZStride + bm*ldC + bn;
        const float* R = res ? res + (long)z*cZStride + bm*ldC + bn : nullptr;
        #pragma unroll
        for (int it = 0; it < 16; it++) {
            int m = tid + it*256;
            int r = m >> 5, i = m & 31;
            float4 v = *(float4*)(dyn + r*RS + i*16);
            if (R) {
                float4 rr = *(const float4*)(R + (long)r*ldC + i*4);
                v.x += rr.x; v.y += rr.y; v.z += rr.z; v.w += rr.w;
            }
            *(float4*)(C + (long)r*ldC + i*4) = v;
        }
    }
}

// ---------------- softmax: fp8 scores -> fp8 probs*512, in place ---------------
__global__ void softmax_f8(uint8_t* __restrict__ S)
{
    uint8_t* p = S + (long)blockIdx.x * HW;
    int tid = threadIdx.x;               // 256 threads * 16 fp8
    uint4 u = ((uint4*)p)[tid];
    uint16_t* hp = (uint16_t*)&u;
    float v[16];
    #pragma unroll
    for (int i = 0; i < 8; i++) {
        __half2 h = e4m3x2_2h(hp[i]);
        v[2*i] = __low2float(h); v[2*i+1] = __high2float(h);
    }
    float mx = -1e30f;
    #pragma unroll
    for (int i = 0; i < 16; i++) mx = fmaxf(mx, v[i]);
    __shared__ float red[256];
    red[tid] = mx; __syncthreads();
    for (int s = 128; s > 0; s >>= 1) {
        if (tid < s) red[tid] = fmaxf(red[tid], red[tid+s]);
        __syncthreads();
    }
    mx = red[0]; __syncthreads();
    float sum = 0.f;
    #pragma unroll
    for (int i = 0; i < 16; i++) { v[i] = __expf(v[i] - mx); sum += v[i]; }
    red[tid] = sum; __syncthreads();
    for (int s = 128; s > 0; s >>= 1) {
        if (tid < s) red[tid] += red[tid+s];
        __syncthreads();
    }
    float inv = 512.f / red[0];
    #pragma unroll
    for (int i = 0; i < 8; i++) hp[i] = f2e4m3x2(v[2*i+1]*inv, v[2*i]*inv);
    ((uint4*)p)[tid] = u;
}

// ---------------- host -----------------------------------------------------------
extern "C" void kernel_launch(void* const* d_in, const int* in_sizes, int n_in,
                              void* d_out, int out_size)
{
    const float* x     = (const float*)d_in[0];
    const float* gamma = (const float*)d_in[1];
    const float* beta  = (const float*)d_in[2];
    const float* Wq    = (const float*)d_in[3];
    const float* bq    = (const float*)d_in[4];
    const float* Wk    = (const float*)d_in[5];
    const float* bk    = (const float*)d_in[6];
    const float* Wv    = (const float*)d_in[7];
    const float* bv    = (const float*)d_in[8];
    const float* Wp    = (const float*)d_in[9];
    const float* bp    = (const float*)d_in[10];
    float* out = (float*)d_out;

    static uint8_t *xn=nullptr, *q=nullptr, *k=nullptr, *vt=nullptr, *att=nullptr, *p8=nullptr;
    static uint8_t *wqt=nullptr, *wkt=nullptr, *wvt=nullptr, *wpt=nullptr;
    static float *mean=nullptr, *rstd=nullptr;
    if (!xn) {
        cudaGetSymbolAddress((void**)&xn,  g_xn);  cudaGetSymbolAddress((void**)&q,   g_q);
        cudaGetSymbolAddress((void**)&k,   g_k);   cudaGetSymbolAddress((void**)&vt,  g_vt);
        cudaGetSymbolAddress((void**)&att, g_att); cudaGetSymbolAddress((void**)&p8,  g_p8);
        cudaGetSymbolAddress((void**)&wqt, g_wqt); cudaGetSymbolAddress((void**)&wkt, g_wkt);
        cudaGetSymbolAddress((void**)&wvt, g_wvt); cudaGetSymbolAddress((void**)&wpt, g_wpt);
        cudaGetSymbolAddress((void**)&mean, g_mean); cudaGetSymbolAddress((void**)&rstd, g_rstd);
        cudaFuncSetAttribute(gemm_f8<false>, cudaFuncAttributeMaxDynamicSharedMemorySize, GEMM_DSMEM);
        cudaFuncSetAttribute(gemm_f8<true>,  cudaFuncAttributeMaxDynamicSharedMemorySize, GEMM_DSMEM);
    }

    const float iw = 1.f/64.f;                   // undo weight x64
    const float sscale = 0.044194173824159216f;  // 1/sqrt(512)

    // launch order: ncu captures launch idx 5 -> scores GEMM
    gn_stats<<<BB*GG, 256>>>(x, mean, rstd);                                    // 0
    gn_apply<<<NPIX*CC/4/256, 256>>>(x, gamma, beta, mean, rstd, xn);           // 1
    wtrans_all<<<dim3(16,16,4), dim3(32,8)>>>(Wq, Wk, Wv, Wp,
                                              wqt, wkt, wvt, wpt);              // 2
    gemm_f8<false><<<dim3(CC/TN, NPIX/TM, 1), 256, GEMM_DSMEM>>>(
        xn, wqt, CC, CC, CC/TK, 0, 0, 0, q, CC, 0, 2, bq, nullptr, nullptr, iw);   // 3
    gemm_f8<false><<<dim3(CC/TN, NPIX/TM, 1), 256, GEMM_DSMEM>>>(
        xn, wkt, CC, CC, CC/TK, 0, 0, 0, k, CC, 0, 2, bk, nullptr, nullptr, iw);   // 4
    // scores = q @ k^T / sqrt(512) -> fp8, f16 accum (ncu target)
    gemm_f8<true><<<dim3(HW/TN, HW/TM, BB), 256, GEMM_DSMEM>>>(
        q, k, CC, CC, CC/TK, HW, HW, 0, p8, HW, (long)HW*HW, 2,
        nullptr, nullptr, nullptr, sscale);                                        // 5
    // vt[c][t] = (Wv^T*64 @ xn)/64 + bv(row)  — A=wvt (512 rows), B=xn (16384 rows)
    gemm_f8<false><<<dim3(NPIX/TN, CC/TM, 1), 256, GEMM_DSMEM>>>(
        wvt, xn, CC, CC, CC/TK, 0, 0, 0, vt, NPIX, 0, 2, nullptr, bv, nullptr, iw);// 6
    softmax_f8<<<BB*HW, 256>>>(p8);                                                // 7
    // att8 = (P*512 @ V)*0.125 = att*64 -> fp8, f16 accum
    gemm_f8<true><<<dim3(CC/TN, HW/TM, BB), 256, GEMM_DSMEM>>>(
        p8, vt, HW, NPIX, HW/TK, HW, 0, HW, att, CC, (long)HW*CC, 2,
        nullptr, nullptr, nullptr, 0.125f);                                        // 8
    // out = (att*64 @ Wp*64)/4096 + bp + x  (fp32)
    gemm_f8<false><<<dim3(CC/TN, NPIX/TM, 1), 256, GEMM_DSMEM>>>(
        att, wpt, CC, CC, CC/TK, 0, 0, 0, out, CC, 0, 1,
        bp, nullptr, x, 1.f/4096.f);                                               // 9
}